// round 1
// baseline (speedup 1.0000x reference)
#include <cuda_runtime.h>
#include <math.h>

// Problem shapes (fixed for MultiLoss_87668872446687)
#define BB 2
#define AA 16384
#define GG 24
#define CC 8
#define THREADS 256
#define BLKS (AA / THREADS)  // 64

// ---------------- scratch (device globals; no allocations) ----------------
__device__ unsigned long long g_gtkey[BB * GG];
__device__ float g_ioumax[BB * AA];
__device__ int   g_iouarg[BB * AA];
__device__ int   g_forced[BB * GG];
__device__ float g_part[BB * BLKS * 4];

// ---------------- helpers ----------------
__device__ __forceinline__ void box_corners(float cx, float cy, float w, float h,
                                            float th, float* px, float* py) {
    float c = cosf(th), s = sinf(th);
    float hw = 0.5f * w, hh = 0.5f * h;
    // CCW: (-hw,-hh), (hw,-hh), (hw,hh), (-hw,hh)
    px[0] = cx + (-hw) * c - (-hh) * s;  py[0] = cy + (-hw) * s + (-hh) * c;
    px[1] = cx + ( hw) * c - (-hh) * s;  py[1] = cy + ( hw) * s + (-hh) * c;
    px[2] = cx + ( hw) * c - ( hh) * s;  py[2] = cy + ( hw) * s + ( hh) * c;
    px[3] = cx + (-hw) * c - ( hh) * s;  py[3] = cy + (-hw) * s + ( hh) * c;
}

// Exact rotated-rect IoU via Sutherland-Hodgman clipping (anchor clipped by gt).
__device__ float rbox_iou(const float* p1x, const float* p1y, float aw, float ah,
                          float gx, float gy, float gw, float gh, float gt) {
    float p2x[4], p2y[4];
    box_corners(gx, gy, gw, gh, gt, p2x, p2y);

    float qx[8], qy[8], ox[8], oy[8];
    int n = 4;
    #pragma unroll
    for (int i = 0; i < 4; i++) { qx[i] = p1x[i]; qy[i] = p1y[i]; }

    #pragma unroll
    for (int e = 0; e < 4; e++) {
        float aex = p2x[e], aey = p2y[e];
        int e2 = (e + 1) & 3;
        float dx = p2x[e2] - aex, dy = p2y[e2] - aey;
        int m = 0;
        for (int i = 0; i < n; i++) {
            float cx = qx[i], cy = qy[i];
            int j = (i + 1 == n) ? 0 : (i + 1);
            float nx = qx[j], ny = qy[j];
            float sc = dx * (cy - aey) - dy * (cx - aex);
            float sn = dx * (ny - aey) - dy * (nx - aex);
            bool ic = (sc >= 0.0f), inn = (sn >= 0.0f);
            if (ic) { ox[m] = cx; oy[m] = cy; m++; }
            if (ic != inn) {
                float t = sc / (sc - sn);  // den != 0 when signs differ
                ox[m] = cx + t * (nx - cx);
                oy[m] = cy + t * (ny - cy);
                m++;
            }
        }
        n = m;
        for (int i = 0; i < n; i++) { qx[i] = ox[i]; qy[i] = oy[i]; }
        if (n == 0) break;
    }

    float cr = 0.0f;
    for (int i = 0; i < n; i++) {
        int j = (i + 1 == n) ? 0 : (i + 1);
        cr += qx[i] * qy[j] - qx[j] * qy[i];
    }
    float inter = 0.5f * fabsf(cr);
    float uni = aw * ah + gw * gh - inter;
    return inter / fmaxf(uni, 1e-9f);
}

__device__ __forceinline__ float smooth_l1(float d) {
    const float beta = 1.0f / 9.0f;
    d = fabsf(d);
    return (d < beta) ? (0.5f * d * d / beta) : (d - 0.5f * beta);
}

__device__ __forceinline__ float balanced_l1(float d) {
    const float bb = 5.0496474644129465f;  // e^(0.9/0.5) - 1
    const float al = 0.5f, ga = 0.9f, beta = 0.5f;
    d = fabsf(d);
    if (d < beta)
        return al / bb * (bb * d + 1.0f) * logf(bb * d / beta + 1.0f) - al * d;
    return ga * d + ga / bb - al * beta;
}

// ---------------- kernels ----------------
__global__ void k_init() {
    int i = threadIdx.x;
    if (i < BB * GG) g_gtkey[i] = 0ull;
}

__global__ void k_pass1(const float* __restrict__ anchors,
                        const float* __restrict__ ann) {
    int b = blockIdx.y;
    int a = blockIdx.x * THREADS + threadIdx.x;

    __shared__ float s_ann[GG * 6];
    if (threadIdx.x < GG * 6) s_ann[threadIdx.x] = ann[b * GG * 6 + threadIdx.x];
    __syncthreads();

    const float* ap = anchors + ((long)(b * AA + a)) * 5;
    float ax = ap[0], ay = ap[1], aw = ap[2], ah = ap[3], at = ap[4];

    float as2 = 0.5f * fmaxf(aw, ah);
    float ax0 = ax - as2, ay0 = ay - as2, ax1 = ax + as2, ay1 = ay + as2;
    float areaA = (ax1 - ax0) * (ay1 - ay0);

    float pcx[4], pcy[4];
    box_corners(ax, ay, aw, ah, at, pcx, pcy);

    float best = -1e30f;
    int bestg = 0;

    for (int g = 0; g < GG; g++) {
        const float* gp = &s_ann[g * 6];
        float iou;
        if (gp[5] == -1.0f) {
            iou = -1.0f;
        } else {
            float gx = gp[0], gy = gp[1], gw = gp[2], gh = gp[3], gth = gp[4];
            float gs2 = 0.5f * fmaxf(gw, gh);
            float gx0 = gx - gs2, gy0 = gy - gs2, gx1 = gx + gs2, gy1 = gy + gs2;
            float lx = fmaxf(ax0, gx0), ly = fmaxf(ay0, gy0);
            float rx = fminf(ax1, gx1), ry = fminf(ay1, gy1);
            float iw = fmaxf(rx - lx, 0.0f), ih = fmaxf(ry - ly, 0.0f);
            float inter = iw * ih;
            float areaG = (gx1 - gx0) * (gy1 - gy0);
            float ind = inter / fmaxf(areaA + areaG - inter, 1e-9f);

            iou = 0.0f;
            if (ind >= 0.1f)
                iou = rbox_iou(pcx, pcy, aw, ah, gx, gy, gw, gh, gth);

            // per-gt argmax over anchors, JAX tie-break (first index wins):
            // iou >= 0 here, so float bits are order-preserving.
            unsigned long long key =
                (((unsigned long long)__float_as_uint(iou)) << 32) |
                (unsigned)(0xFFFFFFFFu - (unsigned)a);
            atomicMax(&g_gtkey[b * GG + g], key);
        }
        if (iou > best) { best = iou; bestg = g; }
    }

    int idx = b * AA + a;
    g_ioumax[idx] = best;
    g_iouarg[idx] = bestg;
}

__global__ void k_pass2(const float* __restrict__ ann) {
    int i = threadIdx.x;
    if (i >= BB * GG) return;
    unsigned long long k = g_gtkey[i];
    float mx = __uint_as_float((unsigned)(k >> 32));
    int arg = (int)(0xFFFFFFFFu - (unsigned)(k & 0xFFFFFFFFull));
    float lab = ann[i * 6 + 5];
    g_forced[i] = (lab != -1.0f && mx < 0.5f) ? arg : -1;
}

__global__ void k_pass3(const float* __restrict__ cls,
                        const float* __restrict__ reg,
                        const float* __restrict__ lmk,
                        const float* __restrict__ anchors,
                        const float* __restrict__ ann,
                        const float* __restrict__ ls) {
    int b = blockIdx.y;
    int a = blockIdx.x * THREADS + threadIdx.x;

    __shared__ float s_ann[GG * 6];
    __shared__ float s_ls[GG * 4];
    __shared__ int s_forced[GG];
    if (threadIdx.x < GG * 6) s_ann[threadIdx.x] = ann[b * GG * 6 + threadIdx.x];
    if (threadIdx.x < GG * 4) s_ls[threadIdx.x] = ls[b * GG * 4 + threadIdx.x];
    if (threadIdx.x < GG) s_forced[threadIdx.x] = g_forced[b * GG + threadIdx.x];
    __syncthreads();

    long idx = (long)b * AA + a;
    float iou_max = g_ioumax[idx];
    int ag = g_iouarg[idx];

    bool pos = (iou_max >= 0.5f);
    #pragma unroll
    for (int g = 0; g < GG; g++)
        if (s_forced[g] == a) pos = true;

    float clssum = 0.0f, regsum = 0.0f, lmksum = 0.0f;

    // ---- focal classification loss ----
    if (pos || iou_max < 0.4f) {
        const float* cp = cls + idx * CC;
        int lab = pos ? (int)s_ann[ag * 6 + 5] : -1;
        #pragma unroll
        for (int c = 0; c < CC; c++) {
            float p = fminf(fmaxf(cp[c], 1e-4f), 1.0f - 1e-4f);
            bool t1 = pos && (c == lab);
            float af = t1 ? 0.25f : 0.75f;
            float q = t1 ? (1.0f - p) : p;
            float fw = af * q * q;
            float bce = t1 ? -logf(p + 1e-6f) : -logf(1.0f - p + 1e-6f);
            clssum += fw * bce;
        }
    }

    // ---- regression (lmr5p) + landmark (balanced L1) ----
    if (pos) {
        const float* apn = anchors + idx * 5;
        float acx = apn[0], acy = apn[1], aw = apn[2], ah = apn[3], ath = apn[4];
        const float* gp = &s_ann[ag * 6];
        float ew = fmaxf(aw, 1.0f), eh = fmaxf(ah, 1.0f);
        float gw = fmaxf(gp[2], 1.0f), gh = fmaxf(gp[3], 1.0f);
        float ta = tanf(ath);
        float dx = 10.0f * (gp[0] - acx) / ew;
        float dy = 10.0f * (gp[1] - acy) / eh;
        float dw = 5.0f * logf(gw / ew);
        float dh = 5.0f * logf(gh / eh);
        float dt = 15.0f * (tanf(gp[4]) - ta);

        const float* rp = reg + idx * 5;
        float r0 = rp[0], r1 = rp[1], r2 = rp[2], r3 = rp[3], r4 = rp[4];

        float tg = r4 / 15.0f + ta;
        if (fabsf(tg) < 1e-4f) tg = (tg < 0.0f) ? -1e-4f : 1e-4f;
        float t22 = 15.0f * (-1.0f / tg - ta);

        float l1 = smooth_l1(dx - r0), l2 = smooth_l1(dy - r1);
        float l3 = smooth_l1(dw - r2), l4 = smooth_l1(dh - r3);
        float l5 = smooth_l1(dw - r3), l6 = smooth_l1(dh - r2);
        float l7 = smooth_l1(dt - r4), l8 = smooth_l1(dt - t22);
        regsum = fminf(l1 + l2 + l3 + l4 + l7, l1 + l2 + l5 + l6 + l8);

        const float* lp = &s_ls[ag * 4];
        float t0 = 10.0f * (lp[0] - acx) / ew;
        float t1_ = 10.0f * (lp[1] - acy) / eh;
        float t2 = 10.0f * (lp[2] - acx) / ew;
        float t3 = 10.0f * (lp[3] - acy) / eh;
        const float* kp = lmk + idx * 4;
        lmksum = balanced_l1(kp[0] - t0) + balanced_l1(kp[1] - t1_) +
                 balanced_l1(kp[2] - t2) + balanced_l1(kp[3] - t3);
    }

    // ---- block reduction of 4 accumulators ----
    __shared__ float red[THREADS * 4];
    red[threadIdx.x] = clssum;
    red[THREADS + threadIdx.x] = regsum;
    red[2 * THREADS + threadIdx.x] = lmksum;
    red[3 * THREADS + threadIdx.x] = pos ? 1.0f : 0.0f;
    __syncthreads();
    for (int st = THREADS / 2; st > 0; st >>= 1) {
        if (threadIdx.x < st) {
            red[threadIdx.x] += red[threadIdx.x + st];
            red[THREADS + threadIdx.x] += red[THREADS + threadIdx.x + st];
            red[2 * THREADS + threadIdx.x] += red[2 * THREADS + threadIdx.x + st];
            red[3 * THREADS + threadIdx.x] += red[3 * THREADS + threadIdx.x + st];
        }
        __syncthreads();
    }
    if (threadIdx.x == 0) {
        float* pp = &g_part[(b * BLKS + blockIdx.x) * 4];
        pp[0] = red[0];
        pp[1] = red[THREADS];
        pp[2] = red[2 * THREADS];
        pp[3] = red[3 * THREADS];
    }
}

__global__ void k_final(float* __restrict__ out) {
    double cm = 0.0, rm = 0.0, lm = 0.0;
    for (int b = 0; b < BB; b++) {
        double cs = 0.0, rs = 0.0, lsm = 0.0, np = 0.0;
        for (int k = 0; k < BLKS; k++) {
            const float* pp = &g_part[(b * BLKS + k) * 4];
            cs += pp[0]; rs += pp[1]; lsm += pp[2]; np += pp[3];
        }
        double denom = (np > 1.0) ? np : 1.0;
        cm += cs / denom;
        if (np > 0.0) {
            rm += rs / (5.0 * denom);
            lm += lsm / (4.0 * denom);
        }
    }
    out[0] = (float)(cm / BB);
    out[1] = (float)(rm / BB);
    out[2] = (float)(lm / BB);
}

// ---------------- launch ----------------
extern "C" void kernel_launch(void* const* d_in, const int* in_sizes, int n_in,
                              void* d_out, int out_size) {
    const float* cls = (const float*)d_in[0];   // (B, A, C)
    const float* reg = (const float*)d_in[1];   // (B, A, 5)
    const float* anc = (const float*)d_in[2];   // (B, A, 5)
    const float* ann = (const float*)d_in[3];   // (B, G, 6)
    const float* lmk = (const float*)d_in[4];   // (B, A, 4)
    const float* ls  = (const float*)d_in[5];   // (B, G, 4)
    float* out = (float*)d_out;                 // 3 floats

    dim3 grid(BLKS, BB);
    k_init<<<1, 64>>>();
    k_pass1<<<grid, THREADS>>>(anc, ann);
    k_pass2<<<1, 64>>>(ann);
    k_pass3<<<grid, THREADS>>>(cls, reg, lmk, anc, ann, ls);
    k_final<<<1, 1>>>(out);
}

// round 2
// speedup vs baseline: 6.9847x; 6.9847x over previous
#include <cuda_runtime.h>
#include <math.h>

// Problem shapes (fixed for MultiLoss_87668872446687)
#define BB 2
#define AA 16384
#define GG 24
#define CC 8

// pass1: warp-per-anchor, lane-per-gt
#define P1_THREADS 256
#define P1_WARPS (P1_THREADS / 32)      // 8 anchors per block
#define P1_BLKX (AA / P1_WARPS)         // 2048

// pass3
#define THREADS 256
#define BLKS (AA / THREADS)             // 64

// ---------------- scratch (device globals; no allocations) ----------------
__device__ unsigned long long g_gtkey[BB * GG];
__device__ float g_ioumax[BB * AA];
__device__ int   g_iouarg[BB * AA];
__device__ int   g_forced[BB * GG];
__device__ float g_part[BB * BLKS * 4];

// ---------------- helpers ----------------
__device__ __forceinline__ float smooth_l1(float d) {
    const float beta = 1.0f / 9.0f;
    d = fabsf(d);
    return (d < beta) ? (0.5f * d * d / beta) : (d - 0.5f * beta);
}

__device__ __forceinline__ float balanced_l1(float d) {
    const float bb = 5.0496474644129465f;  // e^(0.9/0.5) - 1
    const float al = 0.5f, ga = 0.9f, beta = 0.5f;
    d = fabsf(d);
    if (d < beta)
        return al / bb * (bb * d + 1.0f) * logf(bb * d / beta + 1.0f) - al * d;
    return ga * d + ga / bb - al * beta;
}

// ---------------- kernels ----------------
__global__ void k_init() {
    int i = threadIdx.x;
    if (i < BB * GG) g_gtkey[i] = 0ull;
}

// warp per anchor, lane g handles gt g. Clip scratch in conflict-free smem.
__global__ void __launch_bounds__(P1_THREADS) k_pass1(
        const float* __restrict__ anchors,
        const float* __restrict__ ann) {
    __shared__ float s_gw[GG], s_gh[GG];
    __shared__ float s_gx0[GG], s_gy0[GG], s_gx1[GG], s_gy1[GG], s_areaG[GG];
    __shared__ float s_gcx[GG][4], s_gcy[GG][4];
    __shared__ int   s_valid[GG];
    __shared__ unsigned long long s_gtkey[GG];
    __shared__ float sx[16 * P1_THREADS];
    __shared__ float sy[16 * P1_THREADS];

    const int b = blockIdx.y;
    const int tid = threadIdx.x;

    if (tid < GG) {
        const float* gp = ann + (b * GG + tid) * 6;
        float gx = gp[0], gy = gp[1], gw = gp[2], gh = gp[3], gt = gp[4];
        s_valid[tid] = (gp[5] != -1.0f);
        s_gw[tid] = gw; s_gh[tid] = gh;
        float gs2 = 0.5f * fmaxf(gw, gh);
        float x0 = gx - gs2, y0 = gy - gs2, x1 = gx + gs2, y1 = gy + gs2;
        s_gx0[tid] = x0; s_gy0[tid] = y0; s_gx1[tid] = x1; s_gy1[tid] = y1;
        s_areaG[tid] = (x1 - x0) * (y1 - y0);
        float c = cosf(gt), s = sinf(gt);
        float hw = 0.5f * gw, hh = 0.5f * gh;
        s_gcx[tid][0] = gx - hw * c + hh * s;  s_gcy[tid][0] = gy - hw * s - hh * c;
        s_gcx[tid][1] = gx + hw * c + hh * s;  s_gcy[tid][1] = gy + hw * s - hh * c;
        s_gcx[tid][2] = gx + hw * c - hh * s;  s_gcy[tid][2] = gy + hw * s + hh * c;
        s_gcx[tid][3] = gx - hw * c - hh * s;  s_gcy[tid][3] = gy - hw * s + hh * c;
        s_gtkey[tid] = 0ull;
    }
    __syncthreads();

    const int warp = tid >> 5;
    const int lane = tid & 31;
    const int a = blockIdx.x * P1_WARPS + warp;
    const long idx = (long)b * AA + a;

    const float* ap = anchors + idx * 5;
    float ax = ap[0], ay = ap[1], aw = ap[2], ah = ap[3], at = ap[4];

    float as2 = 0.5f * fmaxf(aw, ah);
    float ax0 = ax - as2, ay0 = ay - as2, ax1 = ax + as2, ay1 = ay + as2;
    float areaA = (ax1 - ax0) * (ay1 - ay0);

    // anchor corners (CCW), same arithmetic as reference
    float ac = cosf(at), asn = sinf(at);
    float ahw = 0.5f * aw, ahh = 0.5f * ah;
    float p0x = ax - ahw * ac + ahh * asn, p0y = ay - ahw * asn - ahh * ac;
    float p1x = ax + ahw * ac + ahh * asn, p1y = ay + ahw * asn - ahh * ac;
    float p2x = ax + ahw * ac - ahh * asn, p2y = ay + ahw * asn + ahh * ac;
    float p3x = ax - ahw * ac - ahh * asn, p3y = ay - ahw * asn + ahh * ac;

    const int g = lane;
    unsigned long long keyA = 0ull;

    if (g < GG && s_valid[g]) {
        // axis-aligned square-IoU indicator (gate)
        float lx = fmaxf(ax0, s_gx0[g]), ly = fmaxf(ay0, s_gy0[g]);
        float rx = fminf(ax1, s_gx1[g]), ry = fminf(ay1, s_gy1[g]);
        float iw = fmaxf(rx - lx, 0.0f), ih = fmaxf(ry - ly, 0.0f);
        float inter0 = iw * ih;
        float ind = inter0 / fmaxf(areaA + s_areaG[g] - inter0, 1e-9f);

        float iou = 0.0f;
        if (ind >= 0.1f) {
            // Sutherland-Hodgman clip: anchor quad clipped by gt edges.
            // scratch: slots 0-7 buffer A, 8-15 buffer B; stride P1_THREADS
            // keeps every dynamic access bank-conflict-free.
            #define PXS(bp, i) sx[((bp) + (i)) * P1_THREADS + tid]
            #define PYS(bp, i) sy[((bp) + (i)) * P1_THREADS + tid]
            int cb = 0, ob = 8;
            PXS(cb, 0) = p0x; PYS(cb, 0) = p0y;
            PXS(cb, 1) = p1x; PYS(cb, 1) = p1y;
            PXS(cb, 2) = p2x; PYS(cb, 2) = p2y;
            PXS(cb, 3) = p3x; PYS(cb, 3) = p3y;
            int n = 4;
            #pragma unroll
            for (int e = 0; e < 4; e++) {
                float aex = s_gcx[g][e], aey = s_gcy[g][e];
                int e2 = (e + 1) & 3;
                float dx = s_gcx[g][e2] - aex, dy = s_gcy[g][e2] - aey;
                int m = 0;
                for (int i = 0; i < n; i++) {
                    float cx = PXS(cb, i), cy = PYS(cb, i);
                    int j = (i + 1 == n) ? 0 : (i + 1);
                    float nx = PXS(cb, j), ny = PYS(cb, j);
                    float sc = dx * (cy - aey) - dy * (cx - aex);
                    float sn = dx * (ny - aey) - dy * (nx - aex);
                    bool ic = (sc >= 0.0f), in2 = (sn >= 0.0f);
                    if (ic) { PXS(ob, m) = cx; PYS(ob, m) = cy; m++; }
                    if (ic != in2) {
                        float t = sc / (sc - sn);
                        PXS(ob, m) = cx + t * (nx - cx);
                        PYS(ob, m) = cy + t * (ny - cy);
                        m++;
                    }
                }
                n = m;
                int tmp = cb; cb = ob; ob = tmp;
                if (n == 0) break;
            }
            float cr = 0.0f;
            for (int i = 0; i < n; i++) {
                int j = (i + 1 == n) ? 0 : (i + 1);
                cr += PXS(cb, i) * PYS(cb, j) - PXS(cb, j) * PYS(cb, i);
            }
            float inter = 0.5f * fabsf(cr);
            float uni = aw * ah + s_gw[g] * s_gh[g] - inter;
            iou = inter / fmaxf(uni, 1e-9f);
            #undef PXS
            #undef PYS
        }

        // per-anchor key: tie-break smallest g (JAX argmax first-index)
        unsigned iou_bits = __float_as_uint(iou);  // iou >= 0: order-preserving
        keyA = (((unsigned long long)iou_bits) << 32) |
               (unsigned)(0xFFFFFFFFu - (unsigned)g);
        // per-gt key: tie-break smallest anchor index
        unsigned long long keyG = (((unsigned long long)iou_bits) << 32) |
                                  (unsigned)(0xFFFFFFFFu - (unsigned)a);
        atomicMax(&s_gtkey[g], keyG);
    }

    __syncwarp();
    unsigned long long k = keyA;
    #pragma unroll
    for (int off = 16; off; off >>= 1) {
        unsigned long long o = __shfl_xor_sync(0xFFFFFFFFu, k, off);
        if (o > k) k = o;
    }
    if (lane == 0) {
        g_ioumax[idx] = __uint_as_float((unsigned)(k >> 32));
        g_iouarg[idx] = (int)(0xFFFFFFFFu - (unsigned)(k & 0xFFFFFFFFull));
    }

    __syncthreads();
    if (tid < GG) atomicMax(&g_gtkey[b * GG + tid], s_gtkey[tid]);
}

__global__ void k_pass2(const float* __restrict__ ann) {
    int i = threadIdx.x;
    if (i >= BB * GG) return;
    unsigned long long k = g_gtkey[i];
    float mx = __uint_as_float((unsigned)(k >> 32));
    int arg = (int)(0xFFFFFFFFu - (unsigned)(k & 0xFFFFFFFFull));
    float lab = ann[i * 6 + 5];
    g_forced[i] = (lab != -1.0f && mx < 0.5f) ? arg : -1;
}

__global__ void __launch_bounds__(THREADS) k_pass3(
        const float* __restrict__ cls,
        const float* __restrict__ reg,
        const float* __restrict__ lmk,
        const float* __restrict__ anchors,
        const float* __restrict__ ann,
        const float* __restrict__ ls) {
    int b = blockIdx.y;
    int a = blockIdx.x * THREADS + threadIdx.x;

    __shared__ float s_ann[GG * 6];
    __shared__ float s_ls[GG * 4];
    __shared__ int s_forced[GG];
    if (threadIdx.x < GG * 6) s_ann[threadIdx.x] = ann[b * GG * 6 + threadIdx.x];
    if (threadIdx.x < GG * 4) s_ls[threadIdx.x] = ls[b * GG * 4 + threadIdx.x];
    if (threadIdx.x < GG) s_forced[threadIdx.x] = g_forced[b * GG + threadIdx.x];
    __syncthreads();

    long idx = (long)b * AA + a;
    float iou_max = g_ioumax[idx];
    int ag = g_iouarg[idx];

    bool pos = (iou_max >= 0.5f);
    #pragma unroll
    for (int g = 0; g < GG; g++)
        if (s_forced[g] == a) pos = true;

    float clssum = 0.0f, regsum = 0.0f, lmksum = 0.0f;

    // ---- focal classification loss ----
    if (pos || iou_max < 0.4f) {
        const float* cp = cls + idx * CC;
        int lab = pos ? (int)s_ann[ag * 6 + 5] : -1;
        #pragma unroll
        for (int c = 0; c < CC; c++) {
            float p = fminf(fmaxf(cp[c], 1e-4f), 1.0f - 1e-4f);
            bool t1 = pos && (c == lab);
            float af = t1 ? 0.25f : 0.75f;
            float q = t1 ? (1.0f - p) : p;
            float fw = af * q * q;
            float bce = t1 ? -logf(p + 1e-6f) : -logf(1.0f - p + 1e-6f);
            clssum += fw * bce;
        }
    }

    // ---- regression (lmr5p) + landmark (balanced L1) ----
    if (pos) {
        const float* apn = anchors + idx * 5;
        float acx = apn[0], acy = apn[1], aw = apn[2], ah = apn[3], ath = apn[4];
        const float* gp = &s_ann[ag * 6];
        float ew = fmaxf(aw, 1.0f), eh = fmaxf(ah, 1.0f);
        float gw = fmaxf(gp[2], 1.0f), gh = fmaxf(gp[3], 1.0f);
        float ta = tanf(ath);
        float dx = 10.0f * (gp[0] - acx) / ew;
        float dy = 10.0f * (gp[1] - acy) / eh;
        float dw = 5.0f * logf(gw / ew);
        float dh = 5.0f * logf(gh / eh);
        float dt = 15.0f * (tanf(gp[4]) - ta);

        const float* rp = reg + idx * 5;
        float r0 = rp[0], r1 = rp[1], r2 = rp[2], r3 = rp[3], r4 = rp[4];

        float tg = r4 / 15.0f + ta;
        if (fabsf(tg) < 1e-4f) tg = (tg < 0.0f) ? -1e-4f : 1e-4f;
        float t22 = 15.0f * (-1.0f / tg - ta);

        float l1 = smooth_l1(dx - r0), l2 = smooth_l1(dy - r1);
        float l3 = smooth_l1(dw - r2), l4 = smooth_l1(dh - r3);
        float l5 = smooth_l1(dw - r3), l6 = smooth_l1(dh - r2);
        float l7 = smooth_l1(dt - r4), l8 = smooth_l1(dt - t22);
        regsum = fminf(l1 + l2 + l3 + l4 + l7, l1 + l2 + l5 + l6 + l8);

        const float* lp = &s_ls[ag * 4];
        float t0 = 10.0f * (lp[0] - acx) / ew;
        float t1_ = 10.0f * (lp[1] - acy) / eh;
        float t2 = 10.0f * (lp[2] - acx) / ew;
        float t3 = 10.0f * (lp[3] - acy) / eh;
        const float* kp = lmk + idx * 4;
        lmksum = balanced_l1(kp[0] - t0) + balanced_l1(kp[1] - t1_) +
                 balanced_l1(kp[2] - t2) + balanced_l1(kp[3] - t3);
    }

    // ---- block reduction of 4 accumulators ----
    __shared__ float red[THREADS * 4];
    red[threadIdx.x] = clssum;
    red[THREADS + threadIdx.x] = regsum;
    red[2 * THREADS + threadIdx.x] = lmksum;
    red[3 * THREADS + threadIdx.x] = pos ? 1.0f : 0.0f;
    __syncthreads();
    for (int st = THREADS / 2; st > 0; st >>= 1) {
        if (threadIdx.x < st) {
            red[threadIdx.x] += red[threadIdx.x + st];
            red[THREADS + threadIdx.x] += red[THREADS + threadIdx.x + st];
            red[2 * THREADS + threadIdx.x] += red[2 * THREADS + threadIdx.x + st];
            red[3 * THREADS + threadIdx.x] += red[3 * THREADS + threadIdx.x + st];
        }
        __syncthreads();
    }
    if (threadIdx.x == 0) {
        float* pp = &g_part[(b * BLKS + blockIdx.x) * 4];
        pp[0] = red[0];
        pp[1] = red[THREADS];
        pp[2] = red[2 * THREADS];
        pp[3] = red[3 * THREADS];
    }
}

// 128 threads: warps 0-1 reduce image 0, warps 2-3 image 1 (deterministic order)
__global__ void k_final(float* __restrict__ out) {
    int tid = threadIdx.x;
    int b = tid >> 6;          // 0 or 1
    int k = tid & 63;          // partial index
    const float* pp = &g_part[(b * BLKS + k) * 4];
    float c = pp[0], r = pp[1], l = pp[2], n = pp[3];

    #pragma unroll
    for (int off = 16; off; off >>= 1) {
        c += __shfl_down_sync(0xFFFFFFFFu, c, off);
        r += __shfl_down_sync(0xFFFFFFFFu, r, off);
        l += __shfl_down_sync(0xFFFFFFFFu, l, off);
        n += __shfl_down_sync(0xFFFFFFFFu, n, off);
    }
    __shared__ float w[4][4];  // [warp][val]
    int warp = tid >> 5;
    if ((tid & 31) == 0) {
        w[warp][0] = c; w[warp][1] = r; w[warp][2] = l; w[warp][3] = n;
    }
    __syncthreads();
    if (tid == 0) {
        double cm = 0.0, rm = 0.0, lm = 0.0;
        for (int bb2 = 0; bb2 < BB; bb2++) {
            double cs = (double)w[2 * bb2][0] + (double)w[2 * bb2 + 1][0];
            double rs = (double)w[2 * bb2][1] + (double)w[2 * bb2 + 1][1];
            double lsum = (double)w[2 * bb2][2] + (double)w[2 * bb2 + 1][2];
            double np = (double)w[2 * bb2][3] + (double)w[2 * bb2 + 1][3];
            double denom = (np > 1.0) ? np : 1.0;
            cm += cs / denom;
            if (np > 0.0) {
                rm += rs / (5.0 * denom);
                lm += lsum / (4.0 * denom);
            }
        }
        out[0] = (float)(cm / BB);
        out[1] = (float)(rm / BB);
        out[2] = (float)(lm / BB);
    }
}

// ---------------- launch ----------------
extern "C" void kernel_launch(void* const* d_in, const int* in_sizes, int n_in,
                              void* d_out, int out_size) {
    const float* cls = (const float*)d_in[0];   // (B, A, C)
    const float* reg = (const float*)d_in[1];   // (B, A, 5)
    const float* anc = (const float*)d_in[2];   // (B, A, 5)
    const float* ann = (const float*)d_in[3];   // (B, G, 6)
    const float* lmk = (const float*)d_in[4];   // (B, A, 4)
    const float* ls  = (const float*)d_in[5];   // (B, G, 4)
    float* out = (float*)d_out;                 // 3 floats

    k_init<<<1, 64>>>();
    dim3 grid1(P1_BLKX, BB);
    k_pass1<<<grid1, P1_THREADS>>>(anc, ann);
    k_pass2<<<1, 64>>>(ann);
    dim3 grid3(BLKS, BB);
    k_pass3<<<grid3, THREADS>>>(cls, reg, lmk, anc, ann, ls);
    k_final<<<1, 128>>>(out);
}

// round 3
// speedup vs baseline: 7.4029x; 1.0599x over previous
#include <cuda_runtime.h>
#include <math.h>

// Problem shapes (fixed for MultiLoss_87668872446687)
#define BB 2
#define AA 16384
#define GG 24
#define CC 8
#define TPB 256
#define NBLK (AA / TPB)   // 64 blocks per image
#define QCAP 3072

// ---------------- scratch (device globals; no allocations) ----------------
__device__ unsigned long long g_bkey[BB * NBLK * GG];  // per-block per-gt keys
__device__ float g_part[BB * NBLK * 4];                // per-block loss partials
__device__ float g_ioumax[BB * AA];
__device__ int   g_iouarg[BB * AA];

// ---------------- helpers ----------------
__device__ __forceinline__ float smooth_l1(float d) {
    const float beta = 1.0f / 9.0f;
    d = fabsf(d);
    return (d < beta) ? (0.5f * d * d / beta) : (d - 0.5f * beta);
}

__device__ __forceinline__ float balanced_l1(float d) {
    const float bb = 5.0496474644129465f;  // e^(0.9/0.5) - 1
    const float al = 0.5f, ga = 0.9f, beta = 0.5f;
    d = fabsf(d);
    if (d < beta)
        return al / bb * (bb * d + 1.0f) * logf(bb * d / beta + 1.0f) - al * d;
    return ga * d + ga / bb - al * beta;
}

// focal term for one class probability (already raw, clamps inside)
__device__ __forceinline__ float focal_neg(float p) {
    p = fminf(fmaxf(p, 1e-4f), 1.0f - 1e-4f);
    return 0.75f * p * p * (-logf(1.0f - p + 1e-6f));
}
__device__ __forceinline__ float focal_pos(float p) {
    p = fminf(fmaxf(p, 1e-4f), 1.0f - 1e-4f);
    float q = 1.0f - p;
    return 0.25f * q * q * (-logf(p + 1e-6f));
}

// regression (lmr5p) + landmark (balanced L1) for one positive anchor.
// gp: gt row (6), lp: linestrip row (4), rp: reg row (5), kp: lmk row (4).
__device__ __forceinline__ void pos_losses(
        float acx, float acy, float aw, float ah, float ath,
        const float* gp, const float* lp,
        const float* rp, const float* kp,
        float& regsum, float& lmksum) {
    float ew = fmaxf(aw, 1.0f), eh = fmaxf(ah, 1.0f);
    float gw = fmaxf(gp[2], 1.0f), gh = fmaxf(gp[3], 1.0f);
    float ta = tanf(ath);
    float dx = 10.0f * (gp[0] - acx) / ew;
    float dy = 10.0f * (gp[1] - acy) / eh;
    float dw = 5.0f * logf(gw / ew);
    float dh = 5.0f * logf(gh / eh);
    float dt = 15.0f * (tanf(gp[4]) - ta);

    float r0 = rp[0], r1 = rp[1], r2 = rp[2], r3 = rp[3], r4 = rp[4];

    float tg = r4 / 15.0f + ta;
    if (fabsf(tg) < 1e-4f) tg = (tg < 0.0f) ? -1e-4f : 1e-4f;
    float t22 = 15.0f * (-1.0f / tg - ta);

    float l1 = smooth_l1(dx - r0), l2 = smooth_l1(dy - r1);
    float l3 = smooth_l1(dw - r2), l4 = smooth_l1(dh - r3);
    float l5 = smooth_l1(dw - r3), l6 = smooth_l1(dh - r2);
    float l7 = smooth_l1(dt - r4), l8 = smooth_l1(dt - t22);
    regsum = fminf(l1 + l2 + l3 + l4 + l7, l1 + l2 + l5 + l6 + l8);

    float t0 = 10.0f * (lp[0] - acx) / ew;
    float t1_ = 10.0f * (lp[1] - acy) / eh;
    float t2 = 10.0f * (lp[2] - acx) / ew;
    float t3 = 10.0f * (lp[3] - acy) / eh;
    lmksum = balanced_l1(kp[0] - t0) + balanced_l1(kp[1] - t1_) +
             balanced_l1(kp[2] - t2) + balanced_l1(kp[3] - t3);
}

// ---------------- main kernel: everything per-anchor ----------------
__global__ void __launch_bounds__(TPB) k_main(
        const float* __restrict__ anchors,
        const float* __restrict__ ann,
        const float* __restrict__ cls,
        const float* __restrict__ reg,
        const float* __restrict__ lmk,
        const float* __restrict__ ls) {
    // gt caches
    __shared__ float s_gx0[GG], s_gy0[GG], s_gx1[GG], s_gy1[GG], s_areaG[GG];
    __shared__ float s_gcx[GG][4], s_gcy[GG][4], s_gwh[GG];
    __shared__ float s_gdat[GG][6];
    __shared__ float s_lsd[GG][4];
    __shared__ int   s_valid[GG];
    __shared__ unsigned long long s_gtkey[GG];
    // per-anchor
    __shared__ unsigned long long s_akey[TPB];
    __shared__ float s_ap[5 * TPB];
    // pair queue + clip scratch
    __shared__ unsigned short s_q[QCAP];
    __shared__ int s_qn;
    __shared__ float s_clip[30 * TPB];  // 15 slots x + 15 slots y, tid-strided

    const int b = blockIdx.y;
    const int tid = threadIdx.x;
    const int a = blockIdx.x * TPB + tid;
    const long idx = (long)b * AA + a;

    if (tid == 0) s_qn = 0;
    if (tid < GG) {
        const float* gp = ann + (b * GG + tid) * 6;
        float gx = gp[0], gy = gp[1], gw = gp[2], gh = gp[3], gt = gp[4];
        s_gdat[tid][0] = gx; s_gdat[tid][1] = gy; s_gdat[tid][2] = gw;
        s_gdat[tid][3] = gh; s_gdat[tid][4] = gt; s_gdat[tid][5] = gp[5];
        s_valid[tid] = (gp[5] != -1.0f);
        s_gwh[tid] = gw * gh;
        float gs2 = 0.5f * fmaxf(gw, gh);
        float x0 = gx - gs2, y0 = gy - gs2, x1 = gx + gs2, y1 = gy + gs2;
        s_gx0[tid] = x0; s_gy0[tid] = y0; s_gx1[tid] = x1; s_gy1[tid] = y1;
        s_areaG[tid] = (x1 - x0) * (y1 - y0);
        float c = cosf(gt), s = sinf(gt);
        float hw = 0.5f * gw, hh = 0.5f * gh;
        s_gcx[tid][0] = gx - hw * c + hh * s;  s_gcy[tid][0] = gy - hw * s - hh * c;
        s_gcx[tid][1] = gx + hw * c + hh * s;  s_gcy[tid][1] = gy + hw * s - hh * c;
        s_gcx[tid][2] = gx + hw * c - hh * s;  s_gcy[tid][2] = gy + hw * s + hh * c;
        s_gcx[tid][3] = gx - hw * c - hh * s;  s_gcy[tid][3] = gy - hw * s + hh * c;
        s_gtkey[tid] = 0ull;
        const float* lq = ls + (b * GG + tid) * 4;
        s_lsd[tid][0] = lq[0]; s_lsd[tid][1] = lq[1];
        s_lsd[tid][2] = lq[2]; s_lsd[tid][3] = lq[3];
    }

    // anchor params
    const float* apt = anchors + idx * 5;
    float ax = apt[0], ay = apt[1], aw = apt[2], ah = apt[3], at = apt[4];
    s_ap[0 * TPB + tid] = ax; s_ap[1 * TPB + tid] = ay;
    s_ap[2 * TPB + tid] = aw; s_ap[3 * TPB + tid] = ah;
    s_ap[4 * TPB + tid] = at;

    float as2 = 0.5f * fmaxf(aw, ah);
    float ax0 = ax - as2, ay0 = ay - as2, ax1 = ax + as2, ay1 = ay + as2;
    float areaA = (ax1 - ax0) * (ay1 - ay0);

    __syncthreads();

    // clip lambda: processor tid uses its own scratch column, anchor "al"
    #define SXc(i) s_clip[(i) * TPB + tid]
    #define SYc(i) s_clip[(15 + (i)) * TPB + tid]
    auto do_clip = [&](int al, int g) -> float {
        float bx = s_ap[0 * TPB + al], by = s_ap[1 * TPB + al];
        float bw = s_ap[2 * TPB + al], bh = s_ap[3 * TPB + al];
        float bt = s_ap[4 * TPB + al];
        float c = cosf(bt), s = sinf(bt);
        float hw = 0.5f * bw, hh = 0.5f * bh;
        SXc(0) = bx - hw * c + hh * s;  SYc(0) = by - hw * s - hh * c;
        SXc(1) = bx + hw * c + hh * s;  SYc(1) = by + hw * s - hh * c;
        SXc(2) = bx + hw * c - hh * s;  SYc(2) = by + hw * s + hh * c;
        SXc(3) = bx - hw * c - hh * s;  SYc(3) = by - hw * s + hh * c;
        int n = 4, cb = 0, ob = 8;
        #pragma unroll
        for (int e = 0; e < 4; e++) {
            float aex = s_gcx[g][e], aey = s_gcy[g][e];
            int e2 = (e + 1) & 3;
            float dx = s_gcx[g][e2] - aex, dy = s_gcy[g][e2] - aey;
            int m = 0;
            for (int i = 0; i < n; i++) {
                float cx = SXc(cb + i), cy = SYc(cb + i);
                int j = (i + 1 == n) ? 0 : (i + 1);
                float nx = SXc(cb + j), ny = SYc(cb + j);
                float sc = dx * (cy - aey) - dy * (cx - aex);
                float sn = dx * (ny - aey) - dy * (nx - aex);
                bool ic = (sc >= 0.0f), in2 = (sn >= 0.0f);
                if (ic) { SXc(ob + m) = cx; SYc(ob + m) = cy; m++; }
                if (ic != in2) {
                    float t = sc / (sc - sn);
                    SXc(ob + m) = cx + t * (nx - cx);
                    SYc(ob + m) = cy + t * (ny - cy);
                    m++;
                }
            }
            n = m;
            int tmp = cb; cb = ob; ob = tmp;
            if (n == 0) break;
        }
        float cr = 0.0f;
        for (int i = 0; i < n; i++) {
            int j = (i + 1 == n) ? 0 : (i + 1);
            cr += SXc(cb + i) * SYc(cb + j) - SXc(cb + j) * SYc(cb + i);
        }
        float inter = 0.5f * fabsf(cr);
        float uni = bw * bh + s_gwh[g] - inter;
        return inter / fmaxf(uni, 1e-9f);
    };

    // ---- phase A: indicators + baseline key ----
    unsigned mask = 0;
    unsigned long long bk = 0ull;
    bool anyv = false;
    #pragma unroll
    for (int g = 0; g < GG; g++) {
        if (!s_valid[g]) continue;
        anyv = true;
        unsigned long long k0 = (unsigned long long)(0xFFFFFFFFu - (unsigned)g);
        if (k0 > bk) bk = k0;
        float lx = fmaxf(ax0, s_gx0[g]), ly = fmaxf(ay0, s_gy0[g]);
        float rx = fminf(ax1, s_gx1[g]), ry = fminf(ay1, s_gy1[g]);
        float iw = fmaxf(rx - lx, 0.0f), ih = fmaxf(ry - ly, 0.0f);
        float inter0 = iw * ih;
        float ind = inter0 / fmaxf(areaA + s_areaG[g] - inter0, 1e-9f);
        if (ind >= 0.1f) mask |= (1u << g);
    }
    s_akey[tid] = bk;
    __syncthreads();

    // ---- push passing pairs (inline fallback if queue full; never in practice)
    while (mask) {
        int g = __ffs(mask) - 1;
        mask &= mask - 1;
        int qi = atomicAdd(&s_qn, 1);
        if (qi < QCAP) {
            s_q[qi] = (unsigned short)((tid << 5) | g);
        } else {
            float iou = do_clip(tid, g);
            unsigned long long hb = ((unsigned long long)__float_as_uint(iou)) << 32;
            atomicMax(&s_akey[tid], hb | (unsigned long long)(0xFFFFFFFFu - (unsigned)g));
            atomicMax(&s_gtkey[g], hb | (unsigned long long)(0xFFFFFFFFu - (unsigned)a));
        }
    }
    __syncthreads();

    // ---- phase B: dense clips over queue ----
    int qn = min(s_qn, QCAP);
    for (int i = tid; i < qn; i += TPB) {
        int al = s_q[i] >> 5, g = s_q[i] & 31;
        float iou = do_clip(al, g);
        unsigned long long hb = ((unsigned long long)__float_as_uint(iou)) << 32;
        atomicMax(&s_akey[al], hb | (unsigned long long)(0xFFFFFFFFu - (unsigned)g));
        atomicMax(&s_gtkey[g],
                  hb | (unsigned long long)(0xFFFFFFFFu -
                                            (unsigned)(blockIdx.x * TPB + al)));
    }
    __syncthreads();
    #undef SXc
    #undef SYc

    // ---- phase C: per-anchor losses with pos0 assumption ----
    unsigned long long k = s_akey[tid];
    float iou_max; int ag;
    if (!anyv) { iou_max = -1.0f; ag = 0; }
    else {
        iou_max = __uint_as_float((unsigned)(k >> 32));
        ag = (int)(0xFFFFFFFFu - (unsigned)(k & 0xFFFFFFFFull));
    }
    g_ioumax[idx] = iou_max;
    g_iouarg[idx] = ag;
    bool pos = (iou_max >= 0.5f);

    float clssum = 0.0f, regsum = 0.0f, lmksum = 0.0f;
    if (pos || iou_max < 0.4f) {
        const float* cp = cls + idx * CC;
        int lab = pos ? (int)s_gdat[ag][5] : -1;
        #pragma unroll
        for (int c = 0; c < CC; c++) {
            float p = cp[c];
            clssum += (pos && c == lab) ? focal_pos(p) : focal_neg(p);
        }
    }
    if (pos) {
        pos_losses(ax, ay, aw, ah, at, &s_gdat[ag][0], &s_lsd[ag][0],
                   reg + idx * 5, lmk + idx * 4, regsum, lmksum);
    }

    // ---- block reduction (reuse clip scratch) ----
    float* red = s_clip;
    red[tid] = clssum;
    red[TPB + tid] = regsum;
    red[2 * TPB + tid] = lmksum;
    red[3 * TPB + tid] = pos ? 1.0f : 0.0f;
    __syncthreads();
    for (int st = TPB / 2; st > 0; st >>= 1) {
        if (tid < st) {
            red[tid] += red[tid + st];
            red[TPB + tid] += red[TPB + tid + st];
            red[2 * TPB + tid] += red[2 * TPB + tid + st];
            red[3 * TPB + tid] += red[3 * TPB + tid + st];
        }
        __syncthreads();
    }
    if (tid == 0) {
        float* pp = &g_part[(b * NBLK + blockIdx.x) * 4];
        pp[0] = red[0];
        pp[1] = red[TPB];
        pp[2] = red[2 * TPB];
        pp[3] = red[3 * TPB];
    }
    if (tid < GG)
        g_bkey[(b * NBLK + blockIdx.x) * GG + tid] = s_gtkey[tid];
}

// ---------------- fixer + final reduce (one block, 128 threads) ----------------
__global__ void k_fix(const float* __restrict__ anchors,
                      const float* __restrict__ ann,
                      const float* __restrict__ cls,
                      const float* __restrict__ reg,
                      const float* __restrict__ lmk,
                      const float* __restrict__ ls,
                      float* __restrict__ out) {
    __shared__ float s_mx[BB * GG];
    __shared__ int   s_arg[BB * GG];
    __shared__ int   s_forced[BB * GG];
    __shared__ float s_lab[BB * GG];
    __shared__ float s_dc[BB * GG], s_dr[BB * GG], s_dl[BB * GG];
    __shared__ int   s_dn[BB * GG];
    __shared__ float s_w[4][4];

    int tid = threadIdx.x;

    // per-gt argmax over anchors: reduce the 64 block keys (seed = iou 0, a 0)
    if (tid < BB * GG) {
        int b = tid / GG, g = tid % GG;
        unsigned long long k = 0xFFFFFFFFull;  // key(iou=0, a=0)
        const unsigned long long* bp = &g_bkey[(b * NBLK) * GG + g];
        #pragma unroll 4
        for (int blk = 0; blk < NBLK; blk++) {
            unsigned long long v = bp[blk * GG];
            if (v > k) k = v;
        }
        s_mx[tid] = __uint_as_float((unsigned)(k >> 32));
        s_arg[tid] = (int)(0xFFFFFFFFu - (unsigned)(k & 0xFFFFFFFFull));
        float lab = ann[tid * 6 + 5];
        s_lab[tid] = lab;
        s_forced[tid] = (lab != -1.0f) && (s_mx[tid] < 0.5f);
    }
    __syncthreads();

    // deltas for forced anchors (deduped; skip if already pos0)
    if (tid < BB * GG) {
        s_dc[tid] = 0.0f; s_dr[tid] = 0.0f; s_dl[tid] = 0.0f; s_dn[tid] = 0;
        if (s_forced[tid]) {
            int b = tid / GG;
            int a = s_arg[tid];
            bool unique = true;
            for (int t2 = b * GG; t2 < tid; t2++)
                if (s_forced[t2] && s_arg[t2] == a) unique = false;
            long idx = (long)b * AA + a;
            float imax = g_ioumax[idx];
            if (unique && imax < 0.5f) {
                int ag = g_iouarg[idx];
                const float* gp = ann + (b * GG + ag) * 6;
                const float* cp = cls + idx * CC;
                int lab = (int)gp[5];
                float oldc = 0.0f, newc = 0.0f;
                #pragma unroll
                for (int c = 0; c < CC; c++) {
                    float p = cp[c];
                    float neg = focal_neg(p);
                    if (imax < 0.4f) oldc += neg;
                    newc += (c == lab) ? focal_pos(p) : neg;
                }
                s_dc[tid] = newc - oldc;
                const float* apt = anchors + idx * 5;
                float rsum, lsum;
                pos_losses(apt[0], apt[1], apt[2], apt[3], apt[4],
                           gp, ls + (b * GG + ag) * 4,
                           reg + idx * 5, lmk + idx * 4, rsum, lsum);
                s_dr[tid] = rsum;
                s_dl[tid] = lsum;
                s_dn[tid] = 1;
            }
        }
    }

    // reduce block partials: warps 0-1 -> image 0, warps 2-3 -> image 1
    {
        int b = tid >> 6, kk = tid & 63;
        const float* pp = &g_part[(b * NBLK + kk) * 4];
        float c = pp[0], r = pp[1], l = pp[2], n = pp[3];
        #pragma unroll
        for (int off = 16; off; off >>= 1) {
            c += __shfl_down_sync(0xFFFFFFFFu, c, off);
            r += __shfl_down_sync(0xFFFFFFFFu, r, off);
            l += __shfl_down_sync(0xFFFFFFFFu, l, off);
            n += __shfl_down_sync(0xFFFFFFFFu, n, off);
        }
        int warp = tid >> 5;
        if ((tid & 31) == 0) {
            s_w[warp][0] = c; s_w[warp][1] = r; s_w[warp][2] = l; s_w[warp][3] = n;
        }
    }
    __syncthreads();

    if (tid == 0) {
        double cm = 0.0, rm = 0.0, lm = 0.0;
        for (int b = 0; b < BB; b++) {
            double cs = (double)s_w[2 * b][0] + (double)s_w[2 * b + 1][0];
            double rs = (double)s_w[2 * b][1] + (double)s_w[2 * b + 1][1];
            double lsum = (double)s_w[2 * b][2] + (double)s_w[2 * b + 1][2];
            double np = (double)s_w[2 * b][3] + (double)s_w[2 * b + 1][3];
            bool has_gt = false;
            for (int g = 0; g < GG; g++) {
                int t = b * GG + g;
                if (s_lab[t] != -1.0f) has_gt = true;
                cs += s_dc[t]; rs += s_dr[t]; lsum += s_dl[t];
                np += (double)s_dn[t];
            }
            double denom = (np > 1.0) ? np : 1.0;
            if (has_gt) {
                cm += cs / denom;
                if (np > 0.0) {
                    rm += rs / (5.0 * denom);
                    lm += lsum / (4.0 * denom);
                }
            }
        }
        out[0] = (float)(cm / BB);
        out[1] = (float)(rm / BB);
        out[2] = (float)(lm / BB);
    }
}

// ---------------- launch ----------------
extern "C" void kernel_launch(void* const* d_in, const int* in_sizes, int n_in,
                              void* d_out, int out_size) {
    const float* cls = (const float*)d_in[0];   // (B, A, C)
    const float* reg = (const float*)d_in[1];   // (B, A, 5)
    const float* anc = (const float*)d_in[2];   // (B, A, 5)
    const float* ann = (const float*)d_in[3];   // (B, G, 6)
    const float* lmk = (const float*)d_in[4];   // (B, A, 4)
    const float* ls  = (const float*)d_in[5];   // (B, G, 4)
    float* out = (float*)d_out;                 // 3 floats

    dim3 grid(NBLK, BB);
    k_main<<<grid, TPB>>>(anc, ann, cls, reg, lmk, ls);
    k_fix<<<1, 128>>>(anc, ann, cls, reg, lmk, ls, out);
}